// round 13
// baseline (speedup 1.0000x reference)
#include <cuda_runtime.h>

// SmartDerivatives R13: R11 consumer + WARP-LOCAL double-buffered cp.async.
// Prior staging failures: R3/R7 = CTA-wide barriers; R9 = synchronous relay.
// Here each warp owns a private 2-buffer ring; row k+1 is staged with
// coalesced 8B cp.async (per-thread commit groups, no CTA sync in the loop)
// while row k is consumed from shared via stride-24B LDS.64 (conflict-free:
// 6*lane mod 32 is 16 distinct banks per 16-lane phase). i-side: register
// accum + shfl reduce. j-side: warp-private bins, stride-3 RMW (conflict-free).

constexpr int NA    = 100;
constexpr int D     = 4950;
constexpr int E     = D * 6;
constexpr int S3    = NA * 3;          // 300
constexpr int WARPS = 10;
constexpr int T     = WARPS * 32;      // 320
constexpr int BUF2  = 304;             // float2 slots per buffer (>= 99*3)
constexpr int MAXR  = 10;              // rows per warp

__device__ __forceinline__ unsigned smaddr(const void* p) {
    return (unsigned)__cvta_generic_to_shared(p);
}
__device__ __forceinline__ void cp8(unsigned d, const void* s) {
    asm volatile("cp.async.ca.shared.global [%0], [%1], 8;" :: "r"(d), "l"(s));
}

// issue coalesced 8B cp.async for one triu row (len*3 float2, flat)
__device__ __forceinline__ void stage_row(
    int i, int lane, const float* __restrict__ lb, float2* __restrict__ buf)
{
    const int base = (i * (2 * NA - i - 1)) >> 1;
    const int n2   = (NA - 1 - i) * 3;
    const float2* __restrict__ g2 =
        reinterpret_cast<const float2*>(lb) + (size_t)base * 3;
    for (int k = lane; k < n2; k += 32)
        cp8(smaddr(buf + k), g2 + k);
    asm volatile("cp.async.commit_group;");
}

// consume one staged row from shared
__device__ __forceinline__ void process_row(
    int i, int lane,
    const float2* __restrict__ buf, const float* __restrict__ xb,
    float* __restrict__ ca, float* __restrict__ rowout)
{
    const int base = (i * (2 * NA - i - 1)) >> 1;
    const int len  = NA - 1 - i;

    float r0 = 0.0f, r1 = 0.0f, r2 = 0.0f;

    #pragma unroll 2
    for (int m = lane; m < len; m += 32) {
        const float2 l01 = buf[3 * m + 0];       // LDS.64, conflict-free
        const float2 l23 = buf[3 * m + 1];
        const float2 l45 = buf[3 * m + 2];
        const float  xv  = __ldg(xb + base + m); // coalesced, 1 wf/iter

        r0 = fmaf(l01.x, xv, r0);
        r1 = fmaf(l01.y, xv, r1);
        r2 = fmaf(l23.x, xv, r2);

        float* cj = ca + (i + 1 + m) * 3;        // j unique/lane, stride-3
        cj[0] += l23.y * xv;
        cj[1] += l45.x * xv;
        cj[2] += l45.y * xv;
    }

    #pragma unroll
    for (int off = 16; off; off >>= 1) {
        r0 += __shfl_down_sync(0xffffffffu, r0, off);
        r1 += __shfl_down_sync(0xffffffffu, r1, off);
        r2 += __shfl_down_sync(0xffffffffu, r2, off);
    }
    if (lane == 0) {
        rowout[i * 3 + 0] = r0;
        rowout[i * 3 + 1] = r1;
        rowout[i * 3 + 2] = r2;
    }
}

__global__ void __launch_bounds__(T)
smart_derivatives_kernel(const float* __restrict__ x,
                         const float* __restrict__ left,
                         float* __restrict__ out) {
    __shared__ __align__(16) float2 stage[WARPS][2][BUF2];  // 48.6 KB
    __shared__ float colacc[WARPS][S3];                     // 12 KB
    __shared__ float rowout[S3];                            // 1.2 KB

    const int b    = blockIdx.x;
    const int t    = threadIdx.x;
    const int w    = t >> 5;
    const int lane = t & 31;

    for (int i = t; i < WARPS * S3; i += T) (&colacc[0][0])[i] = 0.0f;
    if (t < S3) rowout[t] = 0.0f;
    __syncthreads();

    const float* __restrict__ lb = left + (size_t)b * E;
    const float* __restrict__ xb = x + (size_t)b * D;
    float* __restrict__ ca = colacc[w];

    // This warp's row list: mirrored pairs per 20-row band (balanced).
    int rows[MAXR];
    int nr = 0;
    #pragma unroll
    for (int base = 0; base < NA - 1; base += 2 * WARPS) {
        const int i1 = base + w;
        const int i2 = base + (2 * WARPS - 1) - w;
        if (i1 < NA - 1) rows[nr++] = i1;
        if (i2 < NA - 1) rows[nr++] = i2;
    }

    // warp-local software pipeline over rows (2-deep cp.async ring)
    stage_row(rows[0], lane, lb, stage[w][0]);
    for (int k = 0; k < nr; ++k) {
        if (k + 1 < nr) {
            stage_row(rows[k + 1], lane, lb, stage[w][(k + 1) & 1]);
            asm volatile("cp.async.wait_group 1;");
        } else {
            asm volatile("cp.async.wait_group 0;");
        }
        __syncwarp();
        process_row(rows[k], lane, stage[w][k & 1], xb, ca, rowout);
        __syncwarp();
    }
    __syncthreads();

    // combine: out(a,d) = (rowout + sum_w colacc[w])^2, coalesced store
    if (t < S3) {
        float s = rowout[t];
        #pragma unroll
        for (int ww = 0; ww < WARPS; ++ww) s += colacc[ww][t];
        out[(size_t)b * S3 + t] = s * s;
    }
}

extern "C" void kernel_launch(void* const* d_in, const int* in_sizes, int n_in,
                              void* d_out, int out_size) {
    const float* x    = (const float*)d_in[0];   // [BATCH, D] fp32
    const float* left = (const float*)d_in[1];   // [BATCH*E] fp32
    (void)in_sizes; (void)n_in; (void)out_size;

    float* out = (float*)d_out;                  // [BATCH, 300] fp32
    smart_derivatives_kernel<<<1024, T>>>(x, left, out);
}